// round 4
// baseline (speedup 1.0000x reference)
#include <cuda_runtime.h>
#include <cuda_bf16.h>

#define NN 50000
#define NE 800000
#define DD 128

// ---------------- scratch (device globals; no allocation) --------------------
__device__ int    g_is64;                   // 1 if edge_index is int64, else int32
__device__ int    g_cnt[NN];                // edge count per row (no self-loop)
__device__ int    g_off[NN];                // CSR row start (exclusive scan)
__device__ int    g_cur[NN];                // scatter cursor
__device__ int    g_col[NE];                // CSR column indices
__device__ float  g_dinv[NN];
__device__ float  g_Wt[DD * DD];            // W1^T : Wt[k*128 + o]
__device__ float4 g_support[NN * DD / 4];   // x @ W1^T + b1
__device__ float  g_s[NN];                  // layer-2 scalar per node (incl b2)
__device__ float  g_ds[NN];                 // dinv[n] * s[n]

// robust index fetch: ei as raw words; which=0 rows, which=1 cols
__device__ __forceinline__ int get_idx(const void* ei, int which, int e) {
    if (g_is64) return (int)((const long long*)ei)[(size_t)which * NE + e];
    return ((const int*)ei)[(size_t)which * NE + e];
}

// ---------------- dtype detection --------------------------------------------
// int64 little-endian with values in [0, 50000): every odd 32-bit word is 0.
// int32 real data: odd words are random indices — OR over 4096 is ~surely != 0.
__global__ void __launch_bounds__(256) k_detect(const int* __restrict__ w) {
    __shared__ int sor[256];
    int t = threadIdx.x, acc = 0;
    for (int i = t; i < 4096; i += 256) acc |= w[2 * i + 1];
    sor[t] = acc;
    __syncthreads();
    for (int d = 128; d; d >>= 1) { if (t < d) sor[t] |= sor[t + d]; __syncthreads(); }
    if (t == 0) g_is64 = (sor[0] == 0) ? 1 : 0;
}

// ---------------- graph preprocessing ----------------------------------------
__global__ void k_init() {
    int n = blockIdx.x * blockDim.x + threadIdx.x;
    if (n < NN) g_cnt[n] = 0;
}

__global__ void k_hist(const void* __restrict__ ei) {
    int e = blockIdx.x * blockDim.x + threadIdx.x;
    if (e < NE) atomicAdd(&g_cnt[get_idx(ei, 0, e)], 1);
}

__global__ void k_dinv() {
    int n = blockIdx.x * blockDim.x + threadIdx.x;
    if (n < NN) g_dinv[n] = rsqrtf((float)(g_cnt[n] + 1));   // +1 self-loop
}

// single block, 1024 threads: exclusive scan of g_cnt -> g_off, g_cur
__global__ void __launch_bounds__(1024) k_scan() {
    __shared__ int ssum[1024];
    const int CH = (NN + 1023) / 1024;           // 49
    int t = threadIdx.x;
    int lo = t * CH, hi = min(lo + CH, NN);
    int s = 0;
    for (int i = lo; i < hi; i++) s += g_cnt[i];
    ssum[t] = s;
    __syncthreads();
    for (int d = 1; d < 1024; d <<= 1) {         // Hillis-Steele inclusive
        int v = (t >= d) ? ssum[t - d] : 0;
        __syncthreads();
        ssum[t] += v;
        __syncthreads();
    }
    int excl = (t == 0) ? 0 : ssum[t - 1];
    for (int i = lo; i < hi; i++) {
        int c = g_cnt[i];
        g_off[i] = excl;
        g_cur[i] = excl;
        excl += c;
    }
}

__global__ void k_scatter(const void* __restrict__ ei) {
    int e = blockIdx.x * blockDim.x + threadIdx.x;
    if (e < NE) {
        int r = get_idx(ei, 0, e);
        int pos = atomicAdd(&g_cur[r], 1);
        g_col[pos] = get_idx(ei, 1, e);
    }
}

__global__ void k_transpose(const float* __restrict__ W1) {
    int idx = blockIdx.x * blockDim.x + threadIdx.x;
    if (idx < DD * DD) {
        int o = idx >> 7, k = idx & 127;
        g_Wt[k * DD + o] = W1[idx];
    }
}

// ---------------- GEMM1: support = x @ W1^T + b1 ------------------------------
// 8 warps/block; warp handles 8 nodes; lane owns features 4*lane..4*lane+3
__global__ void __launch_bounds__(256) k_gemm1(const float* __restrict__ x,
                                               const float* __restrict__ b1) {
    __shared__ float xs[8 * 8 * DD];   // 32 KB
    int tid = threadIdx.x, lane = tid & 31, w = tid >> 5;
    int base = blockIdx.x * 64 + w * 8;
    float* xw = xs + w * 8 * DD;

    #pragma unroll
    for (int m = 0; m < 8; m++) {
        int n = base + m;
        float4 v = make_float4(0.f, 0.f, 0.f, 0.f);
        if (n < NN) v = ((const float4*)x)[n * 32 + lane];
        ((float4*)(xw + m * DD))[lane] = v;
    }
    __syncwarp();

    float4 bb = ((const float4*)b1)[lane];
    float4 acc[8];
    #pragma unroll
    for (int m = 0; m < 8; m++) acc[m] = bb;

    const float4* Wt4 = (const float4*)g_Wt;
    #pragma unroll 4
    for (int k = 0; k < DD; k++) {
        float4 wv = __ldg(&Wt4[k * 32 + lane]);   // L1-resident
        #pragma unroll
        for (int m = 0; m < 8; m++) {
            float xv = xw[m * DD + k];
            acc[m].x += wv.x * xv; acc[m].y += wv.y * xv;
            acc[m].z += wv.z * xv; acc[m].w += wv.w * xv;
        }
    }

    #pragma unroll
    for (int m = 0; m < 8; m++) {
        int n = base + m;
        if (n < NN) g_support[n * 32 + lane] = acc[m];
    }
}

// ---------------- fused layer-1 aggregate + ReLU + W2 dot ---------------------
// one warp per node; lane owns 4 features; register accumulation, no atomics
__global__ void __launch_bounds__(256) k_agg(const float* __restrict__ W2,
                                             const float* __restrict__ b2) {
    int n = (int)((blockIdx.x * blockDim.x + threadIdx.x) >> 5);
    int lane = threadIdx.x & 31;
    if (n >= NN) return;

    float dn = g_dinv[n];
    float4 sv = g_support[n * 32 + lane];                  // self-loop term
    float4 acc = make_float4(sv.x * dn, sv.y * dn, sv.z * dn, sv.w * dn);

    int start = g_off[n];
    int deg   = g_cnt[n];
    for (int base = 0; base < deg; base += 32) {
        int rem = deg - base;
        int cl = 0;
        if (lane < rem) cl = g_col[start + base + lane];   // coalesced chunk
        int lim = rem < 32 ? rem : 32;
        for (int i = 0; i < lim; i++) {
            int   c  = __shfl_sync(0xffffffffu, cl, i);
            float dc = g_dinv[c];
            float4 v = __ldg((const float4*)&g_support[c * 32 + lane]);
            acc.x += dc * v.x; acc.y += dc * v.y;
            acc.z += dc * v.z; acc.w += dc * v.w;
        }
    }

    float4 w2 = __ldg(&((const float4*)W2)[lane]);
    float h0 = fmaxf(acc.x * dn, 0.f), h1 = fmaxf(acc.y * dn, 0.f);
    float h2 = fmaxf(acc.z * dn, 0.f), h3 = fmaxf(acc.w * dn, 0.f);
    float p = h0 * w2.x + h1 * w2.y + h2 * w2.z + h3 * w2.w;
    #pragma unroll
    for (int o = 16; o; o >>= 1) p += __shfl_xor_sync(0xffffffffu, p, o);
    if (lane == 0) {
        float s = p + __ldg(b2);
        g_s[n]  = s;
        g_ds[n] = dn * s;
    }
}

// ---------------- layer 2 via CSR gather --------------------------------------
__global__ void __launch_bounds__(256) k_out(float* __restrict__ out) {
    int n = (int)((blockIdx.x * blockDim.x + threadIdx.x) >> 5);
    int lane = threadIdx.x & 31;
    if (n >= NN) return;
    int start = g_off[n];
    int deg   = g_cnt[n];
    float t = 0.f;
    for (int i = lane; i < deg; i += 32) t += g_ds[g_col[start + i]];
    #pragma unroll
    for (int o = 16; o; o >>= 1) t += __shfl_xor_sync(0xffffffffu, t, o);
    if (lane == 0) {
        float dn = g_dinv[n];
        out[n] = dn * (t + dn * g_s[n]);   // edges + self-loop
    }
}

// ---------------- launch -----------------------------------------------------
extern "C" void kernel_launch(void* const* d_in, const int* in_sizes, int n_in,
                              void* d_out, int out_size) {
    const float* x   = (const float*)d_in[0];
    const void*  ei  = d_in[1];                   // int32 or int64 [2, NE]
    const float* W1  = (const float*)d_in[2];
    const float* b1  = (const float*)d_in[3];
    const float* W2  = (const float*)d_in[4];
    const float* b2  = (const float*)d_in[5];
    float*       out = (float*)d_out;

    k_detect   <<<1, 256>>>((const int*)ei);
    k_init     <<<(NN + 255) / 256, 256>>>();
    k_hist     <<<(NE + 255) / 256, 256>>>(ei);
    k_dinv     <<<(NN + 255) / 256, 256>>>();
    k_scan     <<<1, 1024>>>();
    k_scatter  <<<(NE + 255) / 256, 256>>>(ei);
    k_transpose<<<(DD * DD + 255) / 256, 256>>>(W1);
    k_gemm1    <<<(NN + 63) / 64, 256>>>(x, b1);
    k_agg      <<<(NN * 32 + 255) / 256, 256>>>(W2, b2);
    k_out      <<<(NN * 32 + 255) / 256, 256>>>(out);
}